// round 3
// baseline (speedup 1.0000x reference)
#include <cuda_runtime.h>

#define NODES_MAX 50000
#define D 128

// 25.6 MB scratch for feat @ W (allocation-free rule: __device__ global)
__device__ float g_transformed[(size_t)NODES_MAX * D];

// Fused GEMM: computes  T = feat @ W   and   out = feat @ LW + bias
// as one 50000x128 @ 128x256 GEMM (cols 0..127 -> T, 128..255 -> out).
// 64 rows per block, K-chunked (KC=16) through shared memory.
// Thread t: cg = t&31 handles columns cg + c*32 (conflict-free smem reads,
// coalesced global writes); rg = t>>5 handles rows rg + r*8.
__global__ void gemm_fused(const float* __restrict__ feat,
                           const float* __restrict__ W,
                           const float* __restrict__ LW,
                           const float* __restrict__ bias,
                           float* __restrict__ out, int N) {
    const int R = 64, KC = 16;
    __shared__ float fs[R][KC];    // 4 KB
    __shared__ float ws[KC][256];  // 16 KB
    const int t = threadIdx.x;     // 256 threads
    const int row0 = blockIdx.x * R;
    const int cg = t & 31;
    const int rg = t >> 5;

    float acc[8][8];
#pragma unroll
    for (int r = 0; r < 8; r++)
#pragma unroll
        for (int c = 0; c < 8; c++) acc[r][c] = 0.0f;

    for (int kc = 0; kc < D; kc += KC) {
        // Load weight chunk: column t of [W | LW] for KC k-values (coalesced)
#pragma unroll
        for (int i = 0; i < KC; i++) {
            ws[i][t] = (t < D) ? W[(kc + i) * D + t]
                               : LW[(kc + i) * D + (t - D)];
        }
        // Load feat chunk: 64 rows x 16 k
        for (int i = t; i < R * KC; i += 256) {
            int r = i >> 4, k = i & 15;
            int grow = row0 + r;
            fs[r][k] = (grow < N) ? feat[(size_t)grow * D + kc + k] : 0.0f;
        }
        __syncthreads();

#pragma unroll
        for (int k = 0; k < KC; k++) {
            float wv[8];
#pragma unroll
            for (int c = 0; c < 8; c++) wv[c] = ws[k][cg + c * 32];
#pragma unroll
            for (int r = 0; r < 8; r++) {
                float fv = fs[rg + r * 8][k];
#pragma unroll
                for (int c = 0; c < 8; c++) acc[r][c] += fv * wv[c];
            }
        }
        __syncthreads();
    }

    // Write: cols < 128 -> scratch T, cols >= 128 -> out (+bias).
    // For fixed c, lanes write consecutive columns -> coalesced.
#pragma unroll
    for (int r = 0; r < 8; r++) {
        int grow = row0 + rg + r * 8;
        if (grow >= N) continue;
#pragma unroll
        for (int c = 0; c < 8; c++) {
            int col = cg + c * 32;
            if (col < D)
                g_transformed[(size_t)grow * D + col] = acc[r][c];
            else
                out[(size_t)grow * D + (col - D)] = acc[r][c] + bias[col - D];
        }
    }
}

// Edge scatter: one warp per edge-quad. Each lane owns a float4 (16 B) of the
// 512 B row. All 4 gather loads issued before any reduction (MLP=4), then
// 4 vectorized L2 reductions (red.global.add.v4.f32, sm_90+: no return trip).
__global__ void scatter_edges(const int* __restrict__ src,
                              const int* __restrict__ dst,
                              float* __restrict__ out, int E) {
    const int EPW = 4;
    const int gw = (int)((blockIdx.x * blockDim.x + threadIdx.x) >> 5);
    const int lane = threadIdx.x & 31;
    const int e0 = gw * EPW;
    if (e0 >= E) return;
    const int cnt = (E - e0 < EPW) ? (E - e0) : EPW;

    float4 v[EPW];
    float* p[EPW];
#pragma unroll
    for (int i = 0; i < EPW; i++) {
        if (i < cnt) {
            int s = __ldg(src + e0 + i);
            int d = __ldg(dst + e0 + i);
            v[i] = *reinterpret_cast<const float4*>(
                g_transformed + (size_t)s * D + lane * 4);
            p[i] = out + (size_t)d * D + lane * 4;
        }
    }
#pragma unroll
    for (int i = 0; i < EPW; i++) {
        if (i < cnt) {
            asm volatile(
                "red.global.add.v4.f32 [%0], {%1, %2, %3, %4};"
                :: "l"(p[i]), "f"(v[i].x), "f"(v[i].y), "f"(v[i].z), "f"(v[i].w)
                : "memory");
        }
    }
}

extern "C" void kernel_launch(void* const* d_in, const int* in_sizes, int n_in,
                              void* d_out, int out_size) {
    const float* feat = (const float*)d_in[0];   // [N, 128]
    const float* W    = (const float*)d_in[1];   // [128, 128]
    const float* bias = (const float*)d_in[2];   // [128]
    const float* LW   = (const float*)d_in[3];   // [128, 128]
    const int*   src  = (const int*)d_in[4];     // [E]
    const int*   dst  = (const int*)d_in[5];     // [E]
    float* out = (float*)d_out;                  // [N, 128]

    const int N = in_sizes[0] / D;
    const int E = in_sizes[4];

    // 1) out = feat@LW + bias ; g_transformed = feat@W
    gemm_fused<<<(N + 63) / 64, 256>>>(feat, W, LW, bias, out, N);

    // 2) out[dst] += g_transformed[src]  (stream-ordered after kernel 1)
    const int warps = (E + 3) / 4;
    const int blocks = (warps * 32 + 255) / 256;
    scatter_edges<<<blocks, 256>>>(src, dst, out, E);
}